// round 1
// baseline (speedup 1.0000x reference)
#include <cuda_runtime.h>
#include <cstdint>

#define FULLMASK 0xffffffffu

// ---------------- tile geometry ----------------
// B=8, N=4096, D=128. CTA: 128 q-rows (8 warps x m16), KV block = 64 rows.
// smem (floats): Qs[128][132] | Ks[2][64][132] | Vs[2][64][136]
static constexpr int QSTR = 132;
static constexpr int KSTR = 132;
static constexpr int VSTR = 136;
static constexpr int QS_SZ = 128 * QSTR;      // 16896
static constexpr int KS_SZ = 64 * KSTR;       // 8448
static constexpr int VS_SZ = 64 * VSTR;       // 8704
static constexpr int SMEM_FLOATS = QS_SZ + 2 * KS_SZ + 2 * VS_SZ;  // 51200
static constexpr int SMEM_BYTES  = SMEM_FLOATS * 4;                // 204800

__device__ __forceinline__ uint32_t f2tf32(float f) {
    uint32_t u;
    asm("cvt.rna.tf32.f32 %0, %1;" : "=r"(u) : "f"(f));
    return u;
}

__device__ __forceinline__ void mma_tf32(float c[4],
                                         uint32_t a0, uint32_t a1, uint32_t a2, uint32_t a3,
                                         uint32_t b0, uint32_t b1) {
    asm volatile(
        "mma.sync.aligned.m16n8k8.row.col.f32.tf32.tf32.f32 "
        "{%0,%1,%2,%3}, {%4,%5,%6,%7}, {%8,%9}, {%0,%1,%2,%3};"
        : "+f"(c[0]), "+f"(c[1]), "+f"(c[2]), "+f"(c[3])
        : "r"(a0), "r"(a1), "r"(a2), "r"(a3), "r"(b0), "r"(b1));
}

__device__ __forceinline__ void cp16(uint32_t dst, const float* src) {
    asm volatile("cp.async.cg.shared.global [%0], [%1], 16;" :: "r"(dst), "l"(src));
}

__global__ void __launch_bounds__(256, 1)
fa_tf32_kernel(const float* __restrict__ Q,
               const float* __restrict__ K,
               const float* __restrict__ V,
               float* __restrict__ Out) {
    extern __shared__ float sm[];
    float* Qs = sm;
    float* Ks = sm + QS_SZ;
    float* Vs = sm + QS_SZ + 2 * KS_SZ;

    const int tid = threadIdx.x;
    const int bx  = blockIdx.x;
    // heavy q-blocks first: qb=31 has 64 KV blocks, qb=0 has 2
    const int b  = bx & 7;
    const int qb = 31 - (bx >> 3);
    const int q0 = qb * 128;
    const int jmax = 2 * qb + 1;

    const float scale = 0.08838834764831845f; // 1/sqrt(128)

    // ---- load Q (once), scale + round to tf32 ----
    const float* Qg = Q + ((size_t)b * 4096 + q0) * 128;
    #pragma unroll
    for (int it = 0; it < 16; ++it) {
        int idx = tid + it * 256;            // 0..4095 float4 chunks
        int row = idx >> 5;
        int c4  = (idx & 31) << 2;
        float4 v = *(const float4*)(Qg + row * 128 + c4);
        float* d = Qs + row * QSTR + c4;
        d[0] = __uint_as_float(f2tf32(v.x * scale));
        d[1] = __uint_as_float(f2tf32(v.y * scale));
        d[2] = __uint_as_float(f2tf32(v.z * scale));
        d[3] = __uint_as_float(f2tf32(v.w * scale));
    }

    // ---- async KV loader ----
    auto load_kv = [&](int j, int buf) {
        const float* Kg = K + ((size_t)b * 4096 + j * 64) * 128;
        const float* Vg = V + ((size_t)b * 4096 + j * 64) * 128;
        float* Kd = Ks + buf * KS_SZ;
        float* Vd = Vs + buf * VS_SZ;
        #pragma unroll
        for (int it = 0; it < 8; ++it) {
            int idx = tid + it * 256;        // 0..2047
            int row = idx >> 5;
            int c4  = (idx & 31) << 2;
            cp16((uint32_t)__cvta_generic_to_shared(Kd + row * KSTR + c4),
                 Kg + row * 128 + c4);
        }
        #pragma unroll
        for (int it = 0; it < 8; ++it) {
            int idx = tid + it * 256;
            int row = idx >> 5;
            int c4  = (idx & 31) << 2;
            cp16((uint32_t)__cvta_generic_to_shared(Vd + row * VSTR + c4),
                 Vg + row * 128 + c4);
        }
        asm volatile("cp.async.commit_group;");
    };

    load_kv(0, 0);  // prologue

    const int lane = tid & 31;
    const int warp = tid >> 5;
    const int g = lane >> 2;   // groupID
    const int t = lane & 3;    // tid in group
    const int wr = warp * 16;  // local row base of this warp's m16 tile

    float o_[16][4];
    #pragma unroll
    for (int nf = 0; nf < 16; ++nf)
        #pragma unroll
        for (int i = 0; i < 4; ++i) o_[nf][i] = 0.f;

    float m0 = -1e30f, m1 = -1e30f;   // running row max (rows g, g+8)
    float l0 = 0.f,    l1 = 0.f;      // running row sum

    for (int j = 0; j <= jmax; ++j) {
        float* Kb = Ks + (j & 1) * KS_SZ;
        float* Vb = Vs + (j & 1) * VS_SZ;

        if (j < jmax) {
            load_kv(j + 1, (j + 1) & 1);
            asm volatile("cp.async.wait_group 1;");
        } else {
            asm volatile("cp.async.wait_group 0;");
        }
        __syncthreads();

        // ---- S = Q K^T (scaled) : m16 x n64, k=128 ----
        float s_[8][4];
        #pragma unroll
        for (int nf = 0; nf < 8; ++nf)
            #pragma unroll
            for (int i = 0; i < 4; ++i) s_[nf][i] = 0.f;

        #pragma unroll
        for (int kf = 0; kf < 16; ++kf) {
            const float* qp = Qs + (wr + g) * QSTR + kf * 8 + t;
            uint32_t a0 = __float_as_uint(qp[0]);
            uint32_t a1 = __float_as_uint(qp[8 * QSTR]);
            uint32_t a2 = __float_as_uint(qp[4]);
            uint32_t a3 = __float_as_uint(qp[8 * QSTR + 4]);
            const float* kp = Kb + g * KSTR + kf * 8 + t;
            #pragma unroll
            for (int nf = 0; nf < 8; ++nf) {
                uint32_t b0 = __float_as_uint(kp[nf * 8 * KSTR]);
                uint32_t b1 = __float_as_uint(kp[nf * 8 * KSTR + 4]);
                mma_tf32(s_[nf], a0, a1, a2, a3, b0, b1);
            }
        }

        // ---- causal mask (only the two diagonal-region blocks need it) ----
        if (j * 64 >= q0) {
            const int r0g = q0 + wr + g;
            const int r1g = r0g + 8;
            #pragma unroll
            for (int nf = 0; nf < 8; ++nf) {
                int c0 = j * 64 + nf * 8 + 2 * t;
                if (c0     > r0g) s_[nf][0] = -1e30f;
                if (c0 + 1 > r0g) s_[nf][1] = -1e30f;
                if (c0     > r1g) s_[nf][2] = -1e30f;
                if (c0 + 1 > r1g) s_[nf][3] = -1e30f;
            }
        }

        // ---- online softmax ----
        float mc0 = -1e30f, mc1 = -1e30f;
        #pragma unroll
        for (int nf = 0; nf < 8; ++nf) {
            mc0 = fmaxf(mc0, fmaxf(s_[nf][0], s_[nf][1]));
            mc1 = fmaxf(mc1, fmaxf(s_[nf][2], s_[nf][3]));
        }
        mc0 = fmaxf(mc0, __shfl_xor_sync(FULLMASK, mc0, 1));
        mc0 = fmaxf(mc0, __shfl_xor_sync(FULLMASK, mc0, 2));
        mc1 = fmaxf(mc1, __shfl_xor_sync(FULLMASK, mc1, 1));
        mc1 = fmaxf(mc1, __shfl_xor_sync(FULLMASK, mc1, 2));

        float mn0 = fmaxf(m0, mc0), mn1 = fmaxf(m1, mc1);
        float al0 = __expf(m0 - mn0), al1 = __expf(m1 - mn1);
        m0 = mn0; m1 = mn1;

        float rs0 = 0.f, rs1 = 0.f;
        #pragma unroll
        for (int nf = 0; nf < 8; ++nf) {
            s_[nf][0] = __expf(s_[nf][0] - mn0);
            s_[nf][1] = __expf(s_[nf][1] - mn0);
            s_[nf][2] = __expf(s_[nf][2] - mn1);
            s_[nf][3] = __expf(s_[nf][3] - mn1);
            rs0 += s_[nf][0] + s_[nf][1];
            rs1 += s_[nf][2] + s_[nf][3];
        }
        rs0 += __shfl_xor_sync(FULLMASK, rs0, 1);
        rs0 += __shfl_xor_sync(FULLMASK, rs0, 2);
        rs1 += __shfl_xor_sync(FULLMASK, rs1, 1);
        rs1 += __shfl_xor_sync(FULLMASK, rs1, 2);

        l0 = l0 * al0 + rs0;
        l1 = l1 * al1 + rs1;

        #pragma unroll
        for (int nf = 0; nf < 16; ++nf) {
            o_[nf][0] *= al0; o_[nf][1] *= al0;
            o_[nf][2] *= al1; o_[nf][3] *= al1;
        }

        // ---- O += P @ V : m16 x n128, k=64 ----
        #pragma unroll
        for (int kf = 0; kf < 8; ++kf) {
            float p0 = s_[kf][0], p1 = s_[kf][1], p2 = s_[kf][2], p3 = s_[kf][3];
            // re-shuffle C-layout (cols 2t,2t+1) into A-layout (cols t, t+4)
            int tsrc = (lane & 28) | (t >> 1);
            float u0 = __shfl_sync(FULLMASK, p0, tsrc);
            float u1 = __shfl_sync(FULLMASK, p1, tsrc);
            float u2 = __shfl_sync(FULLMASK, p0, tsrc + 2);
            float u3 = __shfl_sync(FULLMASK, p1, tsrc + 2);
            float w0 = __shfl_sync(FULLMASK, p2, tsrc);
            float w1 = __shfl_sync(FULLMASK, p3, tsrc);
            float w2 = __shfl_sync(FULLMASK, p2, tsrc + 2);
            float w3 = __shfl_sync(FULLMASK, p3, tsrc + 2);
            bool odd = (t & 1);
            uint32_t a0 = f2tf32(odd ? u1 : u0);
            uint32_t a2 = f2tf32(odd ? u3 : u2);
            uint32_t a1 = f2tf32(odd ? w1 : w0);
            uint32_t a3 = f2tf32(odd ? w3 : w2);
            const float* vp = Vb + (kf * 8 + t) * VSTR + g;
            #pragma unroll
            for (int nf = 0; nf < 16; ++nf) {
                uint32_t b0 = __float_as_uint(vp[nf * 8]);
                uint32_t b1 = __float_as_uint(vp[4 * VSTR + nf * 8]);
                mma_tf32(o_[nf], a0, a1, a2, a3, b0, b1);
            }
        }

        __syncthreads();  // protect KV buffer reuse by next iteration's cp.async
    }

    // ---- epilogue: normalize + store ----
    float i0 = 1.f / l0;
    float i1 = 1.f / l1;
    float* Og = Out + ((size_t)b * 4096 + q0 + wr) * 128;
    #pragma unroll
    for (int nf = 0; nf < 16; ++nf) {
        int c = nf * 8 + 2 * t;
        float2 v0 = make_float2(o_[nf][0] * i0, o_[nf][1] * i0);
        float2 v1 = make_float2(o_[nf][2] * i1, o_[nf][3] * i1);
        *(float2*)(Og + g * 128 + c)       = v0;
        *(float2*)(Og + (g + 8) * 128 + c) = v1;
    }
}

extern "C" void kernel_launch(void* const* d_in, const int* in_sizes, int n_in,
                              void* d_out, int out_size) {
    const float* Q = (const float*)d_in[0];
    const float* K = (const float*)d_in[1];
    const float* V = (const float*)d_in[2];
    float* O = (float*)d_out;

    cudaFuncSetAttribute(fa_tf32_kernel,
                         cudaFuncAttributeMaxDynamicSharedMemorySize, SMEM_BYTES);
    fa_tf32_kernel<<<256, 256, SMEM_BYTES>>>(Q, K, V, O);
}

// round 2
// speedup vs baseline: 1.0011x; 1.0011x over previous
#include <cuda_runtime.h>
#include <cstdint>

#define FULLMASK 0xffffffffu

// ---------------- tile geometry ----------------
// B=8, N=4096, D=128. CTA: 128 q-rows (8 warps x m16), KV block = 64 rows.
// smem (floats): Qs[128][132] | Ks[2][64][132] | Vs[2][64][136]
static constexpr int QSTR = 132;
static constexpr int KSTR = 132;
static constexpr int VSTR = 136;
static constexpr int QS_SZ = 128 * QSTR;      // 16896
static constexpr int KS_SZ = 64 * KSTR;       // 8448
static constexpr int VS_SZ = 64 * VSTR;       // 8704
static constexpr int SMEM_FLOATS = QS_SZ + 2 * KS_SZ + 2 * VS_SZ;  // 51200
static constexpr int SMEM_BYTES  = SMEM_FLOATS * 4;                // 204800

__device__ __forceinline__ uint32_t f2tf32(float f) {
    uint32_t u;
    asm("cvt.rna.tf32.f32 %0, %1;" : "=r"(u) : "f"(f));
    return u;
}

__device__ __forceinline__ void mma_tf32(float c[4],
                                         uint32_t a0, uint32_t a1, uint32_t a2, uint32_t a3,
                                         uint32_t b0, uint32_t b1) {
    asm volatile(
        "mma.sync.aligned.m16n8k8.row.col.f32.tf32.tf32.f32 "
        "{%0,%1,%2,%3}, {%4,%5,%6,%7}, {%8,%9}, {%0,%1,%2,%3};"
        : "+f"(c[0]), "+f"(c[1]), "+f"(c[2]), "+f"(c[3])
        : "r"(a0), "r"(a1), "r"(a2), "r"(a3), "r"(b0), "r"(b1));
}

__device__ __forceinline__ void cp16(uint32_t dst, const float* src) {
    asm volatile("cp.async.cg.shared.global [%0], [%1], 16;" :: "r"(dst), "l"(src));
}

__global__ void __launch_bounds__(256, 1)
fa_tf32_kernel(const float* __restrict__ Q,
               const float* __restrict__ K,
               const float* __restrict__ V,
               float* __restrict__ Out) {
    extern __shared__ float sm[];
    float* Qs = sm;
    float* Ks = sm + QS_SZ;
    float* Vs = sm + QS_SZ + 2 * KS_SZ;

    const int tid = threadIdx.x;
    const int bx  = blockIdx.x;
    // heavy q-blocks first: qb=31 has 64 KV blocks, qb=0 has 2
    const int b  = bx & 7;
    const int qb = 31 - (bx >> 3);
    const int q0 = qb * 128;
    const int jmax = 2 * qb + 1;

    const float scale = 0.08838834764831845f; // 1/sqrt(128)

    // ---- load Q (once), scale + round to tf32 ----
    const float* Qg = Q + ((size_t)b * 4096 + q0) * 128;
    #pragma unroll
    for (int it = 0; it < 16; ++it) {
        int idx = tid + it * 256;            // 0..4095 float4 chunks
        int row = idx >> 5;
        int c4  = (idx & 31) << 2;
        float4 v = *(const float4*)(Qg + row * 128 + c4);
        float* d = Qs + row * QSTR + c4;
        d[0] = __uint_as_float(f2tf32(v.x * scale));
        d[1] = __uint_as_float(f2tf32(v.y * scale));
        d[2] = __uint_as_float(f2tf32(v.z * scale));
        d[3] = __uint_as_float(f2tf32(v.w * scale));
    }

    // ---- async KV loader ----
    auto load_kv = [&](int j, int buf) {
        const float* Kg = K + ((size_t)b * 4096 + j * 64) * 128;
        const float* Vg = V + ((size_t)b * 4096 + j * 64) * 128;
        float* Kd = Ks + buf * KS_SZ;
        float* Vd = Vs + buf * VS_SZ;
        #pragma unroll
        for (int it = 0; it < 8; ++it) {
            int idx = tid + it * 256;        // 0..2047
            int row = idx >> 5;
            int c4  = (idx & 31) << 2;
            cp16((uint32_t)__cvta_generic_to_shared(Kd + row * KSTR + c4),
                 Kg + row * 128 + c4);
        }
        #pragma unroll
        for (int it = 0; it < 8; ++it) {
            int idx = tid + it * 256;
            int row = idx >> 5;
            int c4  = (idx & 31) << 2;
            cp16((uint32_t)__cvta_generic_to_shared(Vd + row * VSTR + c4),
                 Vg + row * 128 + c4);
        }
        asm volatile("cp.async.commit_group;");
    };

    load_kv(0, 0);  // prologue

    const int lane = tid & 31;
    const int warp = tid >> 5;
    const int g = lane >> 2;   // groupID
    const int t = lane & 3;    // tid in group
    const int wr = warp * 16;  // local row base of this warp's m16 tile

    float o_[16][4];
    #pragma unroll
    for (int nf = 0; nf < 16; ++nf)
        #pragma unroll
        for (int i = 0; i < 4; ++i) o_[nf][i] = 0.f;

    float m0 = -1e30f, m1 = -1e30f;   // running row max (rows g, g+8)
    float l0 = 0.f,    l1 = 0.f;      // running row sum

    for (int j = 0; j <= jmax; ++j) {
        float* Kb = Ks + (j & 1) * KS_SZ;
        float* Vb = Vs + (j & 1) * VS_SZ;

        if (j < jmax) {
            load_kv(j + 1, (j + 1) & 1);
            asm volatile("cp.async.wait_group 1;");
        } else {
            asm volatile("cp.async.wait_group 0;");
        }
        __syncthreads();

        // ---- S = Q K^T (scaled) : m16 x n64, k=128 ----
        float s_[8][4];
        #pragma unroll
        for (int nf = 0; nf < 8; ++nf)
            #pragma unroll
            for (int i = 0; i < 4; ++i) s_[nf][i] = 0.f;

        #pragma unroll
        for (int kf = 0; kf < 16; ++kf) {
            const float* qp = Qs + (wr + g) * QSTR + kf * 8 + t;
            uint32_t a0 = __float_as_uint(qp[0]);
            uint32_t a1 = __float_as_uint(qp[8 * QSTR]);
            uint32_t a2 = __float_as_uint(qp[4]);
            uint32_t a3 = __float_as_uint(qp[8 * QSTR + 4]);
            const float* kp = Kb + g * KSTR + kf * 8 + t;
            #pragma unroll
            for (int nf = 0; nf < 8; ++nf) {
                uint32_t b0 = __float_as_uint(kp[nf * 8 * KSTR]);
                uint32_t b1 = __float_as_uint(kp[nf * 8 * KSTR + 4]);
                mma_tf32(s_[nf], a0, a1, a2, a3, b0, b1);
            }
        }

        // ---- causal mask (only the two diagonal-region blocks need it) ----
        if (j * 64 >= q0) {
            const int r0g = q0 + wr + g;
            const int r1g = r0g + 8;
            #pragma unroll
            for (int nf = 0; nf < 8; ++nf) {
                int c0 = j * 64 + nf * 8 + 2 * t;
                if (c0     > r0g) s_[nf][0] = -1e30f;
                if (c0 + 1 > r0g) s_[nf][1] = -1e30f;
                if (c0     > r1g) s_[nf][2] = -1e30f;
                if (c0 + 1 > r1g) s_[nf][3] = -1e30f;
            }
        }

        // ---- online softmax ----
        float mc0 = -1e30f, mc1 = -1e30f;
        #pragma unroll
        for (int nf = 0; nf < 8; ++nf) {
            mc0 = fmaxf(mc0, fmaxf(s_[nf][0], s_[nf][1]));
            mc1 = fmaxf(mc1, fmaxf(s_[nf][2], s_[nf][3]));
        }
        mc0 = fmaxf(mc0, __shfl_xor_sync(FULLMASK, mc0, 1));
        mc0 = fmaxf(mc0, __shfl_xor_sync(FULLMASK, mc0, 2));
        mc1 = fmaxf(mc1, __shfl_xor_sync(FULLMASK, mc1, 1));
        mc1 = fmaxf(mc1, __shfl_xor_sync(FULLMASK, mc1, 2));

        float mn0 = fmaxf(m0, mc0), mn1 = fmaxf(m1, mc1);
        float al0 = __expf(m0 - mn0), al1 = __expf(m1 - mn1);
        m0 = mn0; m1 = mn1;

        float rs0 = 0.f, rs1 = 0.f;
        #pragma unroll
        for (int nf = 0; nf < 8; ++nf) {
            s_[nf][0] = __expf(s_[nf][0] - mn0);
            s_[nf][1] = __expf(s_[nf][1] - mn0);
            s_[nf][2] = __expf(s_[nf][2] - mn1);
            s_[nf][3] = __expf(s_[nf][3] - mn1);
            rs0 += s_[nf][0] + s_[nf][1];
            rs1 += s_[nf][2] + s_[nf][3];
        }
        rs0 += __shfl_xor_sync(FULLMASK, rs0, 1);
        rs0 += __shfl_xor_sync(FULLMASK, rs0, 2);
        rs1 += __shfl_xor_sync(FULLMASK, rs1, 1);
        rs1 += __shfl_xor_sync(FULLMASK, rs1, 2);

        l0 = l0 * al0 + rs0;
        l1 = l1 * al1 + rs1;

        #pragma unroll
        for (int nf = 0; nf < 16; ++nf) {
            o_[nf][0] *= al0; o_[nf][1] *= al0;
            o_[nf][2] *= al1; o_[nf][3] *= al1;
        }

        // ---- O += P @ V : m16 x n128, k=64 ----
        #pragma unroll
        for (int kf = 0; kf < 8; ++kf) {
            float p0 = s_[kf][0], p1 = s_[kf][1], p2 = s_[kf][2], p3 = s_[kf][3];
            // re-shuffle C-layout (cols 2t,2t+1) into A-layout (cols t, t+4)
            int tsrc = (lane & 28) | (t >> 1);
            float u0 = __shfl_sync(FULLMASK, p0, tsrc);
            float u1 = __shfl_sync(FULLMASK, p1, tsrc);
            float u2 = __shfl_sync(FULLMASK, p0, tsrc + 2);
            float u3 = __shfl_sync(FULLMASK, p1, tsrc + 2);
            float w0 = __shfl_sync(FULLMASK, p2, tsrc);
            float w1 = __shfl_sync(FULLMASK, p3, tsrc);
            float w2 = __shfl_sync(FULLMASK, p2, tsrc + 2);
            float w3 = __shfl_sync(FULLMASK, p3, tsrc + 2);
            bool odd = (t & 1);
            uint32_t a0 = f2tf32(odd ? u1 : u0);
            uint32_t a2 = f2tf32(odd ? u3 : u2);
            uint32_t a1 = f2tf32(odd ? w1 : w0);
            uint32_t a3 = f2tf32(odd ? w3 : w2);
            const float* vp = Vb + (kf * 8 + t) * VSTR + g;
            #pragma unroll
            for (int nf = 0; nf < 16; ++nf) {
                uint32_t b0 = __float_as_uint(vp[nf * 8]);
                uint32_t b1 = __float_as_uint(vp[4 * VSTR + nf * 8]);
                mma_tf32(o_[nf], a0, a1, a2, a3, b0, b1);
            }
        }

        __syncthreads();  // protect KV buffer reuse by next iteration's cp.async
    }

    // ---- epilogue: normalize + store ----
    float i0 = 1.f / l0;
    float i1 = 1.f / l1;
    float* Og = Out + ((size_t)b * 4096 + q0 + wr) * 128;
    #pragma unroll
    for (int nf = 0; nf < 16; ++nf) {
        int c = nf * 8 + 2 * t;
        float2 v0 = make_float2(o_[nf][0] * i0, o_[nf][1] * i0);
        float2 v1 = make_float2(o_[nf][2] * i1, o_[nf][3] * i1);
        *(float2*)(Og + g * 128 + c)       = v0;
        *(float2*)(Og + (g + 8) * 128 + c) = v1;
    }
}

extern "C" void kernel_launch(void* const* d_in, const int* in_sizes, int n_in,
                              void* d_out, int out_size) {
    const float* Q = (const float*)d_in[0];
    const float* K = (const float*)d_in[1];
    const float* V = (const float*)d_in[2];
    float* O = (float*)d_out;

    cudaFuncSetAttribute(fa_tf32_kernel,
                         cudaFuncAttributeMaxDynamicSharedMemorySize, SMEM_BYTES);
    fa_tf32_kernel<<<256, 256, SMEM_BYTES>>>(Q, K, V, O);
}

// round 3
// speedup vs baseline: 1.0147x; 1.0135x over previous
#include <cuda_runtime.h>
#include <cstdint>

#define FULLMASK 0xffffffffu

// ---------------- tile geometry ----------------
// B=8, N=4096, D=128. CTA: 128 q-rows (8 warps x m16), KV block = 64 rows.
// Q lives in registers. KV: 3-stage ring in smem.
static constexpr int KSTR = 132;
static constexpr int VSTR = 136;
static constexpr int KS_SZ = 64 * KSTR;            // 8448 floats
static constexpr int VS_SZ = 64 * VSTR;            // 8704 floats
static constexpr int STAGE = KS_SZ + VS_SZ;        // 17152 floats per stage
static constexpr int SMEM_FLOATS = 3 * STAGE;      // 51456
static constexpr int SMEM_BYTES  = SMEM_FLOATS * 4; // 205824 bytes

__device__ __forceinline__ uint32_t f2tf32(float f) {
    uint32_t u;
    asm("cvt.rna.tf32.f32 %0, %1;" : "=r"(u) : "f"(f));
    return u;
}

__device__ __forceinline__ float ex2f(float x) {
    float y;
    asm("ex2.approx.f32 %0, %1;" : "=f"(y) : "f"(x));
    return y;
}

// non-volatile: pure register op, lets ptxas interleave with independent math
__device__ __forceinline__ void mma_tf32(float c[4],
                                         uint32_t a0, uint32_t a1, uint32_t a2, uint32_t a3,
                                         uint32_t b0, uint32_t b1) {
    asm("mma.sync.aligned.m16n8k8.row.col.f32.tf32.tf32.f32 "
        "{%0,%1,%2,%3}, {%4,%5,%6,%7}, {%8,%9}, {%0,%1,%2,%3};"
        : "+f"(c[0]), "+f"(c[1]), "+f"(c[2]), "+f"(c[3])
        : "r"(a0), "r"(a1), "r"(a2), "r"(a3), "r"(b0), "r"(b1));
}

__device__ __forceinline__ void cp16(uint32_t dst, const float* src) {
    asm volatile("cp.async.cg.shared.global [%0], [%1], 16;" :: "r"(dst), "l"(src));
}

__global__ void __launch_bounds__(256, 1)
fa_tf32_kernel(const float* __restrict__ Q,
               const float* __restrict__ K,
               const float* __restrict__ V,
               float* __restrict__ Out) {
    extern __shared__ float sm[];

    const int tid  = threadIdx.x;
    const int lane = tid & 31;
    const int warp = tid >> 5;
    const int g    = lane >> 2;   // groupID (row within octet)
    const int t    = lane & 3;    // tid in group
    const int wr   = warp * 16;   // local row base of this warp's m16 tile

    const int bx = blockIdx.x;
    const int b  = bx & 7;
    const int qb = 31 - (bx >> 3);   // heavy q-blocks first
    const int q0 = qb * 128;
    const int jmax = 2 * qb + 1;

    // fold 1/sqrt(128) * log2(e) into Q so softmax uses raw ex2
    const float scale = 0.08838834764831845f * 1.4426950408889634f;

    // ---- Q fragments directly to registers (once) ----
    const float* Qg = Q + ((size_t)b * 4096 + q0 + wr + g) * 128;
    uint32_t q_[16][4];
    #pragma unroll
    for (int kf = 0; kf < 16; ++kf) {
        float x0 = Qg[kf * 8 + t];
        float x1 = Qg[8 * 128 + kf * 8 + t];
        float x2 = Qg[kf * 8 + t + 4];
        float x3 = Qg[8 * 128 + kf * 8 + t + 4];
        q_[kf][0] = f2tf32(x0 * scale);
        q_[kf][1] = f2tf32(x1 * scale);
        q_[kf][2] = f2tf32(x2 * scale);
        q_[kf][3] = f2tf32(x3 * scale);
    }

    // ---- async KV loader (one commit group per call) ----
    auto load_kv = [&](int j, int buf) {
        const float* Kg = K + ((size_t)b * 4096 + j * 64) * 128;
        const float* Vg = V + ((size_t)b * 4096 + j * 64) * 128;
        float* Kd = sm + buf * STAGE;
        float* Vd = Kd + KS_SZ;
        #pragma unroll
        for (int it = 0; it < 8; ++it) {
            int idx = tid + it * 256;
            int row = idx >> 5;
            int c4  = (idx & 31) << 2;
            cp16((uint32_t)__cvta_generic_to_shared(Kd + row * KSTR + c4),
                 Kg + row * 128 + c4);
        }
        #pragma unroll
        for (int it = 0; it < 8; ++it) {
            int idx = tid + it * 256;
            int row = idx >> 5;
            int c4  = (idx & 31) << 2;
            cp16((uint32_t)__cvta_generic_to_shared(Vd + row * VSTR + c4),
                 Vg + row * 128 + c4);
        }
        asm volatile("cp.async.commit_group;");
    };

    // S = Q K^T for one KV block (m16 x n64, k=128), accumulating into sc
    auto S_mma = [&](float sc[8][4], const float* Kb) {
        #pragma unroll
        for (int kf = 0; kf < 16; ++kf) {
            const float* kp = Kb + g * KSTR + kf * 8 + t;
            uint32_t a0 = q_[kf][0], a1 = q_[kf][1], a2 = q_[kf][2], a3 = q_[kf][3];
            #pragma unroll
            for (int nf = 0; nf < 8; ++nf) {
                uint32_t b0 = __float_as_uint(kp[nf * 8 * KSTR]);
                uint32_t b1 = __float_as_uint(kp[nf * 8 * KSTR + 4]);
                mma_tf32(sc[nf], a0, a1, a2, a3, b0, b1);
            }
        }
    };

    // ---- prologue: stages 0,1 in flight; compute S_0 ----
    load_kv(0, 0);
    load_kv(1, 1);
    asm volatile("cp.async.wait_group 1;");
    __syncthreads();

    float s_[8][4];
    #pragma unroll
    for (int nf = 0; nf < 8; ++nf)
        #pragma unroll
        for (int i = 0; i < 4; ++i) s_[nf][i] = 0.f;
    S_mma(s_, sm + 0 * STAGE);

    float o_[16][4];
    #pragma unroll
    for (int nf = 0; nf < 16; ++nf)
        #pragma unroll
        for (int i = 0; i < 4; ++i) o_[nf][i] = 0.f;

    float m0 = -1e30f, m1 = -1e30f;
    float l0 = 0.f,    l1 = 0.f;

    for (int j = 0; ; ++j) {
        const bool has_next = (j < jmax);

        // all warps finished reading stage (j+2)%3 (== stage j-1) last iter
        __syncthreads();
        if (j + 2 <= jmax) load_kv(j + 2, (j + 2) % 3);
        else asm volatile("cp.async.commit_group;");   // keep group counting uniform
        asm volatile("cp.async.wait_group 1;");        // stages j, j+1 resident
        __syncthreads();

        // ---- S_{j+1} (tensor) — independent of softmax_j below; interleaves ----
        float sn[8][4];
        #pragma unroll
        for (int nf = 0; nf < 8; ++nf)
            #pragma unroll
            for (int i = 0; i < 4; ++i) sn[nf][i] = 0.f;
        if (has_next) S_mma(sn, sm + ((j + 1) % 3) * STAGE);

        // ---- causal mask on s_ (diagonal-region blocks only) ----
        if (j * 64 >= q0) {
            const int r0g = q0 + wr + g;
            const int r1g = r0g + 8;
            #pragma unroll
            for (int nf = 0; nf < 8; ++nf) {
                int c0 = j * 64 + nf * 8 + 2 * t;
                if (c0     > r0g) s_[nf][0] = -1e30f;
                if (c0 + 1 > r0g) s_[nf][1] = -1e30f;
                if (c0     > r1g) s_[nf][2] = -1e30f;
                if (c0 + 1 > r1g) s_[nf][3] = -1e30f;
            }
        }

        // ---- online softmax (log2 domain) ----
        float mc0 = -1e30f, mc1 = -1e30f;
        #pragma unroll
        for (int nf = 0; nf < 8; ++nf) {
            mc0 = fmaxf(mc0, fmaxf(s_[nf][0], s_[nf][1]));
            mc1 = fmaxf(mc1, fmaxf(s_[nf][2], s_[nf][3]));
        }
        mc0 = fmaxf(mc0, __shfl_xor_sync(FULLMASK, mc0, 1));
        mc0 = fmaxf(mc0, __shfl_xor_sync(FULLMASK, mc0, 2));
        mc1 = fmaxf(mc1, __shfl_xor_sync(FULLMASK, mc1, 1));
        mc1 = fmaxf(mc1, __shfl_xor_sync(FULLMASK, mc1, 2));

        float mn0 = fmaxf(m0, mc0), mn1 = fmaxf(m1, mc1);
        float al0 = ex2f(m0 - mn0), al1 = ex2f(m1 - mn1);
        m0 = mn0; m1 = mn1;

        float rs0 = 0.f, rs1 = 0.f;
        #pragma unroll
        for (int nf = 0; nf < 8; ++nf) {
            s_[nf][0] = ex2f(s_[nf][0] - mn0);
            s_[nf][1] = ex2f(s_[nf][1] - mn0);
            s_[nf][2] = ex2f(s_[nf][2] - mn1);
            s_[nf][3] = ex2f(s_[nf][3] - mn1);
            rs0 += s_[nf][0] + s_[nf][1];
            rs1 += s_[nf][2] + s_[nf][3];
        }
        rs0 += __shfl_xor_sync(FULLMASK, rs0, 1);
        rs0 += __shfl_xor_sync(FULLMASK, rs0, 2);
        rs1 += __shfl_xor_sync(FULLMASK, rs1, 1);
        rs1 += __shfl_xor_sync(FULLMASK, rs1, 2);

        l0 = l0 * al0 + rs0;
        l1 = l1 * al1 + rs1;

        #pragma unroll
        for (int nf = 0; nf < 16; ++nf) {
            o_[nf][0] *= al0; o_[nf][1] *= al0;
            o_[nf][2] *= al1; o_[nf][3] *= al1;
        }

        // ---- O += P @ V : m16 x n128, k=64 ----
        {
            const float* Vb = sm + (j % 3) * STAGE + KS_SZ;
            #pragma unroll
            for (int kf = 0; kf < 8; ++kf) {
                float p0 = s_[kf][0], p1 = s_[kf][1], p2 = s_[kf][2], p3 = s_[kf][3];
                // re-shuffle C-layout (cols 2t,2t+1) into A-layout (cols t, t+4)
                int tsrc = (lane & 28) | (t >> 1);
                float u0 = __shfl_sync(FULLMASK, p0, tsrc);
                float u1 = __shfl_sync(FULLMASK, p1, tsrc);
                float u2 = __shfl_sync(FULLMASK, p0, tsrc + 2);
                float u3 = __shfl_sync(FULLMASK, p1, tsrc + 2);
                float w0 = __shfl_sync(FULLMASK, p2, tsrc);
                float w1 = __shfl_sync(FULLMASK, p3, tsrc);
                float w2 = __shfl_sync(FULLMASK, p2, tsrc + 2);
                float w3 = __shfl_sync(FULLMASK, p3, tsrc + 2);
                bool odd = (t & 1);
                uint32_t a0 = f2tf32(odd ? u1 : u0);
                uint32_t a2 = f2tf32(odd ? u3 : u2);
                uint32_t a1 = f2tf32(odd ? w1 : w0);
                uint32_t a3 = f2tf32(odd ? w3 : w2);
                const float* vp = Vb + (kf * 8 + t) * VSTR + g;
                #pragma unroll
                for (int nf = 0; nf < 16; ++nf) {
                    uint32_t b0 = __float_as_uint(vp[nf * 8]);
                    uint32_t b1 = __float_as_uint(vp[4 * VSTR + nf * 8]);
                    mma_tf32(o_[nf], a0, a1, a2, a3, b0, b1);
                }
            }
        }

        if (!has_next) break;

        #pragma unroll
        for (int nf = 0; nf < 8; ++nf)
            #pragma unroll
            for (int i = 0; i < 4; ++i) s_[nf][i] = sn[nf][i];
    }

    // ---- epilogue: normalize + store ----
    float i0 = 1.f / l0;
    float i1 = 1.f / l1;
    float* Og = Out + ((size_t)b * 4096 + q0 + wr) * 128;
    #pragma unroll
    for (int nf = 0; nf < 16; ++nf) {
        int c = nf * 8 + 2 * t;
        float2 v0 = make_float2(o_[nf][0] * i0, o_[nf][1] * i0);
        float2 v1 = make_float2(o_[nf][2] * i1, o_[nf][3] * i1);
        *(float2*)(Og + g * 128 + c)       = v0;
        *(float2*)(Og + (g + 8) * 128 + c) = v1;
    }
}

extern "C" void kernel_launch(void* const* d_in, const int* in_sizes, int n_in,
                              void* d_out, int out_size) {
    const float* Q = (const float*)d_in[0];
    const float* K = (const float*)d_in[1];
    const float* V = (const float*)d_in[2];
    float* O = (float*)d_out;

    cudaFuncSetAttribute(fa_tf32_kernel,
                         cudaFuncAttributeMaxDynamicSharedMemorySize, SMEM_BYTES);
    fa_tf32_kernel<<<256, 256, SMEM_BYTES>>>(Q, K, V, O);
}

// round 4
// speedup vs baseline: 1.0169x; 1.0022x over previous
#include <cuda_runtime.h>
#include <cstdint>

#define FULLMASK 0xffffffffu

// ---------------- tile geometry ----------------
// B=8, N=4096, D=128. CTA: 128 q-rows (8 warps x m16), KV block = 64 rows.
// Q lives in registers. KV: 3-stage ring in smem.
static constexpr int KSTR = 132;
static constexpr int VSTR = 136;
static constexpr int KS_SZ = 64 * KSTR;            // 8448 floats
static constexpr int VS_SZ = 64 * VSTR;            // 8704 floats
static constexpr int STAGE = KS_SZ + VS_SZ;        // 17152 floats per stage
static constexpr int SMEM_FLOATS = 3 * STAGE;      // 51456
static constexpr int SMEM_BYTES  = SMEM_FLOATS * 4; // 205824 bytes

__device__ __forceinline__ uint32_t f2tf32(float f) {
    uint32_t u;
    asm("cvt.rna.tf32.f32 %0, %1;" : "=r"(u) : "f"(f));
    return u;
}

__device__ __forceinline__ float ex2f(float x) {
    float y;
    asm("ex2.approx.f32 %0, %1;" : "=f"(y) : "f"(x));
    return y;
}

// non-volatile: pure register op, lets ptxas interleave with independent math
__device__ __forceinline__ void mma_tf32(float c[4],
                                         uint32_t a0, uint32_t a1, uint32_t a2, uint32_t a3,
                                         uint32_t b0, uint32_t b1) {
    asm("mma.sync.aligned.m16n8k8.row.col.f32.tf32.tf32.f32 "
        "{%0,%1,%2,%3}, {%4,%5,%6,%7}, {%8,%9}, {%0,%1,%2,%3};"
        : "+f"(c[0]), "+f"(c[1]), "+f"(c[2]), "+f"(c[3])
        : "r"(a0), "r"(a1), "r"(a2), "r"(a3), "r"(b0), "r"(b1));
}

__device__ __forceinline__ void cp16(uint32_t dst, const float* src) {
    asm volatile("cp.async.cg.shared.global [%0], [%1], 16;" :: "r"(dst), "l"(src));
}

__global__ void __launch_bounds__(256, 1)
fa_tf32_kernel(const float* __restrict__ Q,
               const float* __restrict__ K,
               const float* __restrict__ V,
               float* __restrict__ Out) {
    extern __shared__ float sm[];

    const int tid  = threadIdx.x;
    const int lane = tid & 31;
    const int warp = tid >> 5;
    const int g    = lane >> 2;   // groupID (row within octet)
    const int t    = lane & 3;    // tid in group
    const int wr   = warp * 16;   // local row base of this warp's m16 tile

    const int bx = blockIdx.x;
    const int b  = bx & 7;
    const int qb = 31 - (bx >> 3);   // heavy q-blocks first
    const int q0 = qb * 128;
    const int jmax = 2 * qb + 1;

    // fold 1/sqrt(128) * log2(e) into Q so softmax uses raw ex2
    const float scale = 0.08838834764831845f * 1.4426950408889634f;

    // ---- Q fragments directly to registers (once) ----
    const float* Qg = Q + ((size_t)b * 4096 + q0 + wr + g) * 128;
    uint32_t q_[16][4];
    #pragma unroll
    for (int kf = 0; kf < 16; ++kf) {
        float x0 = Qg[kf * 8 + t];
        float x1 = Qg[8 * 128 + kf * 8 + t];
        float x2 = Qg[kf * 8 + t + 4];
        float x3 = Qg[8 * 128 + kf * 8 + t + 4];
        q_[kf][0] = f2tf32(x0 * scale);
        q_[kf][1] = f2tf32(x1 * scale);
        q_[kf][2] = f2tf32(x2 * scale);
        q_[kf][3] = f2tf32(x3 * scale);
    }

    // ---- async KV loader (one commit group per call) ----
    auto load_kv = [&](int j, int buf) {
        const float* Kg = K + ((size_t)b * 4096 + j * 64) * 128;
        const float* Vg = V + ((size_t)b * 4096 + j * 64) * 128;
        float* Kd = sm + buf * STAGE;
        float* Vd = Kd + KS_SZ;
        #pragma unroll
        for (int it = 0; it < 8; ++it) {
            int idx = tid + it * 256;
            int row = idx >> 5;
            int c4  = (idx & 31) << 2;
            cp16((uint32_t)__cvta_generic_to_shared(Kd + row * KSTR + c4),
                 Kg + row * 128 + c4);
        }
        #pragma unroll
        for (int it = 0; it < 8; ++it) {
            int idx = tid + it * 256;
            int row = idx >> 5;
            int c4  = (idx & 31) << 2;
            cp16((uint32_t)__cvta_generic_to_shared(Vd + row * VSTR + c4),
                 Vg + row * 128 + c4);
        }
        asm volatile("cp.async.commit_group;");
    };

    // S = Q K^T for one KV block (m16 x n64, k=128), accumulating into sc
    auto S_mma = [&](float sc[8][4], const float* Kb) {
        #pragma unroll
        for (int kf = 0; kf < 16; ++kf) {
            const float* kp = Kb + g * KSTR + kf * 8 + t;
            uint32_t a0 = q_[kf][0], a1 = q_[kf][1], a2 = q_[kf][2], a3 = q_[kf][3];
            #pragma unroll
            for (int nf = 0; nf < 8; ++nf) {
                uint32_t b0 = __float_as_uint(kp[nf * 8 * KSTR]);
                uint32_t b1 = __float_as_uint(kp[nf * 8 * KSTR + 4]);
                mma_tf32(sc[nf], a0, a1, a2, a3, b0, b1);
            }
        }
    };

    // ---- prologue: stages 0,1 in flight; compute S_0 ----
    load_kv(0, 0);
    load_kv(1, 1);
    asm volatile("cp.async.wait_group 1;");
    __syncthreads();

    float s_[8][4];
    #pragma unroll
    for (int nf = 0; nf < 8; ++nf)
        #pragma unroll
        for (int i = 0; i < 4; ++i) s_[nf][i] = 0.f;
    S_mma(s_, sm + 0 * STAGE);

    float o_[16][4];
    #pragma unroll
    for (int nf = 0; nf < 16; ++nf)
        #pragma unroll
        for (int i = 0; i < 4; ++i) o_[nf][i] = 0.f;

    float m0 = -1e30f, m1 = -1e30f;
    float l0 = 0.f,    l1 = 0.f;

    for (int j = 0; ; ++j) {
        const bool has_next = (j < jmax);

        // all warps finished reading stage (j+2)%3 (== stage j-1) last iter
        __syncthreads();
        if (j + 2 <= jmax) load_kv(j + 2, (j + 2) % 3);
        else asm volatile("cp.async.commit_group;");   // keep group counting uniform
        asm volatile("cp.async.wait_group 1;");        // stages j, j+1 resident
        __syncthreads();

        // ---- S_{j+1} (tensor) — independent of softmax_j below; interleaves ----
        float sn[8][4];
        #pragma unroll
        for (int nf = 0; nf < 8; ++nf)
            #pragma unroll
            for (int i = 0; i < 4; ++i) sn[nf][i] = 0.f;
        if (has_next) S_mma(sn, sm + ((j + 1) % 3) * STAGE);

        // ---- causal mask on s_ (diagonal-region blocks only) ----
        if (j * 64 >= q0) {
            const int r0g = q0 + wr + g;
            const int r1g = r0g + 8;
            #pragma unroll
            for (int nf = 0; nf < 8; ++nf) {
                int c0 = j * 64 + nf * 8 + 2 * t;
                if (c0     > r0g) s_[nf][0] = -1e30f;
                if (c0 + 1 > r0g) s_[nf][1] = -1e30f;
                if (c0     > r1g) s_[nf][2] = -1e30f;
                if (c0 + 1 > r1g) s_[nf][3] = -1e30f;
            }
        }

        // ---- online softmax (log2 domain) ----
        float mc0 = -1e30f, mc1 = -1e30f;
        #pragma unroll
        for (int nf = 0; nf < 8; ++nf) {
            mc0 = fmaxf(mc0, fmaxf(s_[nf][0], s_[nf][1]));
            mc1 = fmaxf(mc1, fmaxf(s_[nf][2], s_[nf][3]));
        }
        mc0 = fmaxf(mc0, __shfl_xor_sync(FULLMASK, mc0, 1));
        mc0 = fmaxf(mc0, __shfl_xor_sync(FULLMASK, mc0, 2));
        mc1 = fmaxf(mc1, __shfl_xor_sync(FULLMASK, mc1, 1));
        mc1 = fmaxf(mc1, __shfl_xor_sync(FULLMASK, mc1, 2));

        float mn0 = fmaxf(m0, mc0), mn1 = fmaxf(m1, mc1);
        float al0 = ex2f(m0 - mn0), al1 = ex2f(m1 - mn1);
        m0 = mn0; m1 = mn1;

        float rs0 = 0.f, rs1 = 0.f;
        #pragma unroll
        for (int nf = 0; nf < 8; ++nf) {
            s_[nf][0] = ex2f(s_[nf][0] - mn0);
            s_[nf][1] = ex2f(s_[nf][1] - mn0);
            s_[nf][2] = ex2f(s_[nf][2] - mn1);
            s_[nf][3] = ex2f(s_[nf][3] - mn1);
            rs0 += s_[nf][0] + s_[nf][1];
            rs1 += s_[nf][2] + s_[nf][3];
        }
        rs0 += __shfl_xor_sync(FULLMASK, rs0, 1);
        rs0 += __shfl_xor_sync(FULLMASK, rs0, 2);
        rs1 += __shfl_xor_sync(FULLMASK, rs1, 1);
        rs1 += __shfl_xor_sync(FULLMASK, rs1, 2);

        l0 = l0 * al0 + rs0;
        l1 = l1 * al1 + rs1;

        #pragma unroll
        for (int nf = 0; nf < 16; ++nf) {
            o_[nf][0] *= al0; o_[nf][1] *= al0;
            o_[nf][2] *= al1; o_[nf][3] *= al1;
        }

        // ---- O += P @ V : m16 x n128, k=64 ----
        {
            const float* Vb = sm + (j % 3) * STAGE + KS_SZ;
            #pragma unroll
            for (int kf = 0; kf < 8; ++kf) {
                float p0 = s_[kf][0], p1 = s_[kf][1], p2 = s_[kf][2], p3 = s_[kf][3];
                // re-shuffle C-layout (cols 2t,2t+1) into A-layout (cols t, t+4)
                int tsrc = (lane & 28) | (t >> 1);
                float u0 = __shfl_sync(FULLMASK, p0, tsrc);
                float u1 = __shfl_sync(FULLMASK, p1, tsrc);
                float u2 = __shfl_sync(FULLMASK, p0, tsrc + 2);
                float u3 = __shfl_sync(FULLMASK, p1, tsrc + 2);
                float w0 = __shfl_sync(FULLMASK, p2, tsrc);
                float w1 = __shfl_sync(FULLMASK, p3, tsrc);
                float w2 = __shfl_sync(FULLMASK, p2, tsrc + 2);
                float w3 = __shfl_sync(FULLMASK, p3, tsrc + 2);
                bool odd = (t & 1);
                uint32_t a0 = f2tf32(odd ? u1 : u0);
                uint32_t a2 = f2tf32(odd ? u3 : u2);
                uint32_t a1 = f2tf32(odd ? w1 : w0);
                uint32_t a3 = f2tf32(odd ? w3 : w2);
                const float* vp = Vb + (kf * 8 + t) * VSTR + g;
                #pragma unroll
                for (int nf = 0; nf < 16; ++nf) {
                    uint32_t b0 = __float_as_uint(vp[nf * 8]);
                    uint32_t b1 = __float_as_uint(vp[4 * VSTR + nf * 8]);
                    mma_tf32(o_[nf], a0, a1, a2, a3, b0, b1);
                }
            }
        }

        if (!has_next) break;

        #pragma unroll
        for (int nf = 0; nf < 8; ++nf)
            #pragma unroll
            for (int i = 0; i < 4; ++i) s_[nf][i] = sn[nf][i];
    }

    // ---- epilogue: normalize + store ----
    float i0 = 1.f / l0;
    float i1 = 1.f / l1;
    float* Og = Out + ((size_t)b * 4096 + q0 + wr) * 128;
    #pragma unroll
    for (int nf = 0; nf < 16; ++nf) {
        int c = nf * 8 + 2 * t;
        float2 v0 = make_float2(o_[nf][0] * i0, o_[nf][1] * i0);
        float2 v1 = make_float2(o_[nf][2] * i1, o_[nf][3] * i1);
        *(float2*)(Og + g * 128 + c)       = v0;
        *(float2*)(Og + (g + 8) * 128 + c) = v1;
    }
}

extern "C" void kernel_launch(void* const* d_in, const int* in_sizes, int n_in,
                              void* d_out, int out_size) {
    const float* Q = (const float*)d_in[0];
    const float* K = (const float*)d_in[1];
    const float* V = (const float*)d_in[2];
    float* O = (float*)d_out;

    cudaFuncSetAttribute(fa_tf32_kernel,
                         cudaFuncAttributeMaxDynamicSharedMemorySize, SMEM_BYTES);
    fa_tf32_kernel<<<256, 256, SMEM_BYTES>>>(Q, K, V, O);
}